// round 17
// baseline (speedup 1.0000x reference)
#include <cuda_runtime.h>
#include <cuda_fp16.h>
#include <cstdint>

#define NB 64
#define TB 1024
#define IB 88
#define HB 1024

#define NCTA 128        // 4 batch-quarters x 32 col-groups
#define RT2 288         // 8 mma warps + 1 control warp

// rnn2 smem byte offsets
#define SM_W    0        // W^2 hi frag-packed 64KB, then lo 64KB
#define SM_A    131072   // chain0 hi 32KB, chain1 hi 32KB
#define SM_RED  196608   // 8 warps * 2 chains * 512 floats = 32KB
#define SM_MBAR 229376   // 4 chunk mbarriers
#define SM_TOT  229440

// device scratch
__device__ __align__(256)  float g_ih[(size_t)NB * TB * HB];   // ih[n][t][h]
__device__ __align__(256)  float g_z [(size_t)NB * TB * HB];   // z[n][t][h] = W*ih_t + ih_{t+1}
__device__ __align__(256)  float g_W2[(size_t)HB * HB];        // W^2 fp32
__device__ __align__(256)  float g_h1[(size_t)NB * HB];        // h_1 fp32
__device__ __align__(256)  unsigned char g_wf_hi[2097152];     // W fp16 hi, B-frag packed
__device__ __align__(256)  unsigned char g_wf_lo[2097152];     // W fp16 lo
// A images: [buf][chain][quarter][ktile 64][lane 32][16B]
__device__ __align__(1024) unsigned char g_ha[2][2][4][32768];
__device__ unsigned g_arrive, g_epoch;

// ---- ptx helpers (baseline PTX only) ----
__device__ __forceinline__ void mbinit(uint32_t m, uint32_t c) {
    asm volatile("mbarrier.init.shared.b64 [%0], %1;" :: "r"(m), "r"(c) : "memory");
}
__device__ __forceinline__ void mbexpect(uint32_t m, uint32_t b) {
    asm volatile("mbarrier.arrive.expect_tx.shared.b64 _, [%0], %1;" :: "r"(m), "r"(b) : "memory");
}
__device__ __forceinline__ void mwait(uint32_t m, uint32_t par) {
    asm volatile(
        "{\n\t.reg .pred P;\n"
        "W%=:\n\t"
        "mbarrier.try_wait.parity.shared::cta.b64 P, [%0], %1, 0x989680;\n\t"
        "@P bra D%=;\n\t"
        "bra W%=;\n"
        "D%=:\n\t}" :: "r"(m), "r"(par) : "memory");
}
__device__ __forceinline__ void bulkcp8k(uint32_t dst, const void* src, uint32_t mbar) {
    asm volatile(
        "cp.async.bulk.shared::cluster.global.mbarrier::complete_tx::bytes [%0], [%1], %2, [%3];"
        :: "r"(dst), "l"(src), "r"(8192u), "r"(mbar) : "memory");
}
__device__ __forceinline__ void gbar(unsigned b) {
    unsigned old;
    asm volatile("atom.release.gpu.global.add.u32 %0, [%1], 1;"
                 : "=r"(old) : "l"(&g_arrive) : "memory");
    if (old + 1u == b * (unsigned)NCTA) {
        asm volatile("st.release.gpu.global.u32 [%0], %1;" :: "l"(&g_epoch), "r"(b) : "memory");
    } else {
        unsigned e;
        do {
            asm volatile("ld.acquire.gpu.global.u32 %0, [%1];" : "=r"(e) : "l"(&g_epoch) : "memory");
        } while (e < b);
    }
}
__device__ __forceinline__ void mma_f32(float c[4], const uint32_t a[4], uint32_t b0, uint32_t b1) {
    asm volatile(
        "mma.sync.aligned.m16n8k16.row.col.f32.f16.f16.f32 "
        "{%0,%1,%2,%3}, {%4,%5,%6,%7}, {%8,%9}, {%0,%1,%2,%3};"
        : "+f"(c[0]), "+f"(c[1]), "+f"(c[2]), "+f"(c[3])
        : "r"(a[0]), "r"(a[1]), "r"(a[2]), "r"(a[3]), "r"(b0), "r"(b1));
}
__device__ __forceinline__ uint32_t packh(float a, float b) {
    return (uint32_t)__half_as_ushort(__float2half_rn(a)) |
           ((uint32_t)__half_as_ushort(__float2half_rn(b)) << 16);
}
__device__ __forceinline__ void split2f(float a, float b, uint32_t& hi, uint32_t& lo) {
    __half ha = __float2half_rn(a), hb = __float2half_rn(b);
    hi = (uint32_t)__half_as_ushort(ha) | ((uint32_t)__half_as_ushort(hb) << 16);
    lo = packh(a - __half2float(ha), b - __half2float(hb));
}

// ---- kernel 1: ih = x @ W_ih^T + b (fp32 SIMT); resets barrier state ----
__global__ __launch_bounds__(256) void ih_kernel(const float* __restrict__ x,
                                                 const float* __restrict__ W_ih,
                                                 const float* __restrict__ b_ih) {
    if (blockIdx.x == 0 && blockIdx.y == 0 && threadIdx.x == 0) {
        g_arrive = 0u; g_epoch = 0u;
    }
    extern __shared__ float smf[];
    float* xs = smf;
    float* wt = smf + IB * 64;
    const int jb = blockIdx.x * 128, mb = blockIdx.y * 64, tid = threadIdx.x;
    for (int e = tid; e < 64 * IB; e += 256) {
        int m = e / IB, i = e - m * IB;
        xs[i * 64 + m] = x[(size_t)(mb + m) * IB + i];
    }
    for (int e = tid; e < 128 * IB; e += 256) {
        int j = e / IB, i = e - j * IB;
        wt[i * 128 + j] = W_ih[(size_t)(jb + j) * IB + i];
    }
    __syncthreads();
    const int jo = (tid & 15) * 8, mo = (tid >> 4) * 4;
    float acc[4][8];
#pragma unroll
    for (int jj = 0; jj < 8; jj++) {
        float b = b_ih[jb + jo + jj];
        acc[0][jj] = b; acc[1][jj] = b; acc[2][jj] = b; acc[3][jj] = b;
    }
#pragma unroll 4
    for (int i = 0; i < IB; i++) {
        float4 xv = *(const float4*)&xs[i * 64 + mo];
        float4 w0 = *(const float4*)&wt[i * 128 + jo];
        float4 w1 = *(const float4*)&wt[i * 128 + jo + 4];
        float xm[4] = {xv.x, xv.y, xv.z, xv.w};
#pragma unroll
        for (int mm = 0; mm < 4; mm++) {
            acc[mm][0] += xm[mm] * w0.x; acc[mm][1] += xm[mm] * w0.y;
            acc[mm][2] += xm[mm] * w0.z; acc[mm][3] += xm[mm] * w0.w;
            acc[mm][4] += xm[mm] * w1.x; acc[mm][5] += xm[mm] * w1.y;
            acc[mm][6] += xm[mm] * w1.z; acc[mm][7] += xm[mm] * w1.w;
        }
    }
#pragma unroll
    for (int mm = 0; mm < 4; mm++) {
        size_t row = (size_t)(mb + mo + mm) * HB + jb + jo;
        *(float4*)&g_ih[row]     = make_float4(acc[mm][0], acc[mm][1], acc[mm][2], acc[mm][3]);
        *(float4*)&g_ih[row + 4] = make_float4(acc[mm][4], acc[mm][5], acc[mm][6], acc[mm][7]);
    }
}

// ---- kernel 2: W2 = W*W (fp32 SIMT, 64x128 tiles) ----
__global__ __launch_bounds__(256) void w2_kernel(const float* __restrict__ W) {
    __shared__ float At[64 * 64];    // At[kc*64+m] = W[mb+m][kb+kc]
    __shared__ float Bt[64 * 128];   // Bt[kc*128+j] = W[kb+kc][jb+j]
    const int jb = blockIdx.x * 128, mb = blockIdx.y * 64, tid = threadIdx.x;
    const int jo = (tid & 15) * 8, mo = (tid >> 4) * 4;
    float acc[4][8];
#pragma unroll
    for (int mm = 0; mm < 4; mm++)
#pragma unroll
        for (int jj = 0; jj < 8; jj++) acc[mm][jj] = 0.f;

    for (int kb = 0; kb < HB; kb += 64) {
        __syncthreads();
        for (int e = tid; e < 64 * 64; e += 256) {
            int kc = e & 63, m = e >> 6;
            At[kc * 64 + m] = W[(size_t)(mb + m) * HB + kb + kc];
        }
        for (int e = tid; e < 64 * 128; e += 256) {
            int j = e & 127, kc = e >> 7;
            Bt[kc * 128 + j] = W[(size_t)(kb + kc) * HB + jb + j];
        }
        __syncthreads();
#pragma unroll 4
        for (int kc = 0; kc < 64; kc++) {
            float4 av = *(const float4*)&At[kc * 64 + mo];
            float4 b0 = *(const float4*)&Bt[kc * 128 + jo];
            float4 b1 = *(const float4*)&Bt[kc * 128 + jo + 4];
            float am[4] = {av.x, av.y, av.z, av.w};
#pragma unroll
            for (int mm = 0; mm < 4; mm++) {
                acc[mm][0] += am[mm] * b0.x; acc[mm][1] += am[mm] * b0.y;
                acc[mm][2] += am[mm] * b0.z; acc[mm][3] += am[mm] * b0.w;
                acc[mm][4] += am[mm] * b1.x; acc[mm][5] += am[mm] * b1.y;
                acc[mm][6] += am[mm] * b1.z; acc[mm][7] += am[mm] * b1.w;
            }
        }
    }
#pragma unroll
    for (int mm = 0; mm < 4; mm++) {
        size_t row = (size_t)(mb + mo + mm) * HB + jb + jo;
        *(float4*)&g_W2[row]     = make_float4(acc[mm][0], acc[mm][1], acc[mm][2], acc[mm][3]);
        *(float4*)&g_W2[row + 4] = make_float4(acc[mm][4], acc[mm][5], acc[mm][6], acc[mm][7]);
    }
}

// ---- kernel 3: prepack W fp16 limbs into B-fragment gmem layout ----
__global__ __launch_bounds__(1024) void wprep_kernel(const float* __restrict__ W) {
    int e = blockIdx.x * 1024 + threadIdx.x;   // grid 1024 -> 1M elements
    int n = e >> 10, k = e & 1023;
    float w = W[(size_t)n * HB + k];
    __half hv = __float2half_rn(w);
    __half lv = __float2half_rn(w - __half2float(hv));
    int ntG = n >> 3, nn = n & 7, kt = k >> 4, kk = k & 15;
    int lf = nn * 4 + ((kk >> 1) & 3);
    uint32_t off = (uint32_t)(((ntG * 64 + kt) * 32 + lf) * 8 + (kk >> 3) * 4 + (kk & 1) * 2);
    *(unsigned short*)(g_wf_hi + off) = __half_as_ushort(hv);
    *(unsigned short*)(g_wf_lo + off) = __half_as_ushort(lv);
}

// ---- kernel 4: z = ih @ W^T (+ shifted ih), 3-term split HMMA; also h1 ----
// grid (8 col-tiles, 513 row-tiles). y<512: z rows [128y..128y+128).
// y==512: h1[n][:] = W*(initial+ih_0)[n] + ih_0[n][:]  (64 rows, warps 0-3)
__global__ __launch_bounds__(256) void z_kernel(const float* __restrict__ initial) {
    const int gx = blockIdx.x, gy = blockIdx.y;
    const int tid = threadIdx.x, wid = tid >> 5, lane = tid & 31;
    const bool h1 = (gy == 512);
    if (h1 && wid >= 4) return;

    const int rloc = wid * 16 + (lane >> 2);          // local row (lo)
    const int c0l = (lane & 3) * 2;                   // k within ktile / n within ntile
    float c[16][4];
#pragma unroll
    for (int nt = 0; nt < 16; nt++) { c[nt][0]=0.f; c[nt][1]=0.f; c[nt][2]=0.f; c[nt][3]=0.f; }

    // A row pointers (fp32)
    const float* arow0;
    const float* arow1;
    const float* brow0 = nullptr;   // initial rows (h1 only)
    const float* brow1 = nullptr;
    if (h1) {
        int n0 = rloc;
        arow0 = g_ih + (size_t)n0 * TB * HB;          // ih[n][0][:]
        arow1 = g_ih + (size_t)(n0 + 8) * TB * HB;
        brow0 = initial + (size_t)n0 * HB;
        brow1 = initial + (size_t)(n0 + 8) * HB;
    } else {
        size_t r0 = (size_t)gy * 128 + rloc;
        arow0 = g_ih + r0 * HB;
        arow1 = g_ih + (r0 + 8) * HB;
    }

#pragma unroll 2
    for (int kt = 0; kt < 64; kt++) {
        int k0 = kt * 16 + c0l;
        float2 x0 = *(const float2*)(arow0 + k0);
        float2 x1 = *(const float2*)(arow1 + k0);
        float2 x2 = *(const float2*)(arow0 + k0 + 8);
        float2 x3 = *(const float2*)(arow1 + k0 + 8);
        if (h1) {
            float2 i0 = *(const float2*)(brow0 + k0);
            float2 i1 = *(const float2*)(brow1 + k0);
            float2 i2 = *(const float2*)(brow0 + k0 + 8);
            float2 i3 = *(const float2*)(brow1 + k0 + 8);
            x0.x += i0.x; x0.y += i0.y; x1.x += i1.x; x1.y += i1.y;
            x2.x += i2.x; x2.y += i2.y; x3.x += i3.x; x3.y += i3.y;
        }
        uint32_t ah[4], al[4];
        split2f(x0.x, x0.y, ah[0], al[0]);
        split2f(x1.x, x1.y, ah[1], al[1]);
        split2f(x2.x, x2.y, ah[2], al[2]);
        split2f(x3.x, x3.y, ah[3], al[3]);
#pragma unroll
        for (int nt = 0; nt < 16; nt++) {
            uint32_t boff = (uint32_t)((((gx * 16 + nt) * 64 + kt) * 32 + lane) * 8);
            uint32_t bh0, bh1, bl0, bl1;
            asm volatile("ld.global.v2.u32 {%0,%1}, [%2];"
                : "=r"(bh0), "=r"(bh1) : "l"(g_wf_hi + boff));
            asm volatile("ld.global.v2.u32 {%0,%1}, [%2];"
                : "=r"(bl0), "=r"(bl1) : "l"(g_wf_lo + boff));
            mma_f32(c[nt], ah, bh0, bh1);   // hi*hi
            mma_f32(c[nt], al, bh0, bh1);   // lo*hi
            mma_f32(c[nt], ah, bl0, bl1);   // hi*lo
        }
    }

    // epilogue
    if (h1) {
        int n0 = rloc;
#pragma unroll
        for (int nt = 0; nt < 16; nt++) {
            int j = gx * 128 + nt * 8 + c0l;
            float i00 = g_ih[(size_t)n0 * TB * HB + j];
            float i01 = g_ih[(size_t)n0 * TB * HB + j + 1];
            float i10 = g_ih[(size_t)(n0 + 8) * TB * HB + j];
            float i11 = g_ih[(size_t)(n0 + 8) * TB * HB + j + 1];
            *(float2*)(g_h1 + (size_t)n0 * HB + j)       = make_float2(c[nt][0] + i00, c[nt][1] + i01);
            *(float2*)(g_h1 + (size_t)(n0 + 8) * HB + j) = make_float2(c[nt][2] + i10, c[nt][3] + i11);
        }
    } else {
        size_t r0 = (size_t)gy * 128 + rloc;
        size_t r1 = r0 + 8;
        int t0 = (int)(r0 & 1023), t1 = (int)(r1 & 1023);
#pragma unroll
        for (int nt = 0; nt < 16; nt++) {
            int j = gx * 128 + nt * 8 + c0l;
            float a0 = c[nt][0], a1 = c[nt][1], a2 = c[nt][2], a3 = c[nt][3];
            if (t0 < 1023) {
                float2 nx = *(const float2*)(g_ih + (r0 + 1) * HB + j);
                a0 += nx.x; a1 += nx.y;
            }
            if (t1 < 1023) {
                float2 nx = *(const float2*)(g_ih + (r1 + 1) * HB + j);
                a2 += nx.x; a3 += nx.y;
            }
            *(float2*)(g_z + r0 * HB + j) = make_float2(a0, a1);
            *(float2*)(g_z + r1 * HB + j) = make_float2(a2, a3);
        }
    }
}

// ---- kernel 5: persistent W^2 recurrence, 2 chains, 2-term split (R16 core) ----
__global__ __launch_bounds__(RT2, 1)
void rnn2_kernel(const float* __restrict__ initial, float* __restrict__ out, int two) {
    extern __shared__ __align__(1024) unsigned char sm[];
    const uint32_t smb = (uint32_t)__cvta_generic_to_shared(sm);
    const int tid = threadIdx.x, wid = tid >> 5, lane = tid & 31;
    const int bid = blockIdx.x;
    const int q = bid >> 5, g = bid & 31, jb = g * 32;
    float* red = (float*)(sm + SM_RED);
    const uint32_t mb0 = smb + SM_MBAR;
    const size_t NTH = (size_t)NB * TB * HB;

    if (tid == 0)
        for (int ch = 0; ch < 4; ch++) mbinit(mb0 + ch * 8, 1);

    // stage W^2 slice, fragment-packed fp16 limbs
    for (int e = tid; e < 32 * HB; e += RT2) {
        int n = e >> 10, k = e & (HB - 1);
        float w = g_W2[(size_t)(jb + n) * HB + k];
        __half hv = __float2half_rn(w);
        __half lv = __float2half_rn(w - __half2float(hv));
        int nt = n >> 3, nn = n & 7, kt = k >> 4, kk = k & 15;
        int lf = nn * 4 + ((kk >> 1) & 3);
        uint32_t off = (uint32_t)(((nt * 64 + kt) * 32 + lf) * 8 + (kk >> 3) * 4 + (kk & 1) * 2);
        *(unsigned short*)(sm + SM_W + off)         = __half_as_ushort(hv);
        *(unsigned short*)(sm + SM_W + 65536 + off) = __half_as_ushort(lv);
    }

    // ---- step 0: h_0 (chain0) and h_1 (chain1): out + images buf0 ----
    for (int e = tid; e < 1024; e += RT2) {
        int c = e >> 9, o = e & 511;
        int row = o >> 5, j = o & 31, jg = jb + j, n0 = q * 16 + row;
        float v;
        if (c == 0) v = initial[(size_t)n0 * HB + jg] + g_ih[(size_t)n0 * TB * HB + jg];
        else        v = g_h1[(size_t)n0 * HB + jg];
        out[((size_t)n0 * TB + c) * HB + jg] = v;
        if (two) out[NTH + ((size_t)n0 * TB + c) * HB + jg] = v;
        int kt = jg >> 4, kk = jg & 15;
        int la = ((row & 7) << 2) | ((kk >> 1) & 3);
        int rg = ((row >> 3) & 1) | ((kk >> 3) << 1);
        uint32_t off = (uint32_t)(kt * 512 + la * 16 + rg * 4 + (kk & 1) * 2);
        *(unsigned short*)(&g_ha[0][c][q][off]) = __half_as_ushort(__float2half_rn(v));
    }
    asm volatile("fence.proxy.async;" ::: "memory");
    __syncthreads();

    // ---- preload B-hi (W^2) fragments into registers ----
    uint32_t bh[4][8][2];
    if (wid < 8) {
#pragma unroll
        for (int nt = 0; nt < 4; nt++)
#pragma unroll
            for (int kt = 0; kt < 8; kt++) {
                uint32_t boff = smb + SM_W +
                    (uint32_t)(((nt * 64 + wid * 8 + kt) * 32 + lane) * 8);
                asm volatile("ld.shared.v2.u32 {%0,%1}, [%2];"
                    : "=r"(bh[nt][kt][0]), "=r"(bh[nt][kt][1]) : "r"(boff));
            }
    }

    // epilogue constants (per chain): thread j handles outputs 2j, 2j+1
    const int ent = tid >> 6;
    const int elane = (tid >> 1) & 31;
    const int eip = tid & 1;
    const int erow = (elane >> 2) + eip * 8;
    const int ecol = ent * 8 + (elane & 3) * 2;
    const int en0 = q * 16 + erow;
    const int ejg = jb + ecol;
    const int ebase = ent * 128 + elane * 4 + 2 * eip;
    const int ikt = ejg >> 4, ikk = ejg & 15;
    const int ila = ((erow & 7) << 2) | ((ikk >> 1) & 3);
    const int irg = ((erow >> 3) & 1) | ((ikk >> 3) << 1);
    const uint32_t ioff = (uint32_t)(ikt * 512 + ila * 16 + irg * 4);

    for (int s = 1; s < 512; s++) {
        const uint32_t par = (uint32_t)((s - 1) & 1);
        const int te = 2 * s, to = 2 * s + 1;
        if (wid == 8) {
            // -------- control warp --------
            if (lane == 0) {
                asm volatile("fence.proxy.async;" ::: "memory");
                gbar((unsigned)s);
                const unsigned char* e0 = &g_ha[(s - 1) & 1][0][q][0];
                const unsigned char* e1 = &g_ha[(s - 1) & 1][1][q][0];
#pragma unroll
                for (int ch = 0; ch < 4; ch++) {
                    mbexpect(mb0 + ch * 8, 16384u);
                    bulkcp8k(smb + SM_A + ch * 8192,         e0 + ch * 8192, mb0 + ch * 8);
                    bulkcp8k(smb + SM_A + 32768 + ch * 8192, e1 + ch * 8192, mb0 + ch * 8);
                }
            }
            __syncthreads();   // reduce-sync
            __syncthreads();   // end-sync
        } else {
            // -------- mma warps: 2 chains x 4 nt x 8 kt x 2 terms --------
            float2 ue = *(const float2*)(g_z + ((size_t)en0 * TB + (te - 2)) * HB + ejg);
            float2 uo = *(const float2*)(g_z + ((size_t)en0 * TB + (to - 2)) * HB + ejg);

            float c0[4][4], c1[4][4];
#pragma unroll
            for (int nt = 0; nt < 4; nt++) {
                c0[nt][0]=0.f; c0[nt][1]=0.f; c0[nt][2]=0.f; c0[nt][3]=0.f;
                c1[nt][0]=0.f; c1[nt][1]=0.f; c1[nt][2]=0.f; c1[nt][3]=0.f;
            }

            mwait(mb0 + (wid >> 1) * 8, par);
            uint32_t a0off = smb + SM_A + (uint32_t)(wid * 8) * 512 + lane * 16;
            uint32_t a1off = a0off + 32768u;
#pragma unroll
            for (int kt = 0; kt < 8; kt++) {
                uint32_t a0[4], a1[4];
                asm volatile("ld.shared.v4.u32 {%0,%1,%2,%3}, [%4];"
                    : "=r"(a0[0]), "=r"(a0[1]), "=r"(a0[2]), "=r"(a0[3]) : "r"(a0off));
                asm volatile("ld.shared.v4.u32 {%0,%1,%2,%3}, [%4];"
                    : "=r"(a1[0]), "=r"(a1[1]), "=r"(a1[2]), "=r"(a1[3]) : "r"(a1off));
#pragma unroll
                for (int nt = 0; nt < 4; nt++) {
                    uint32_t bl0, bl1;
                    uint32_t bloff = smb + SM_W + 65536u +
                        (uint32_t)(((nt * 64 + wid * 8 + kt) * 32 + lane) * 8);
                    asm volatile("ld.shared.v2.u32 {%0,%1}, [%2];"
                        : "=r"(bl0), "=r"(bl1) : "r"(bloff));
                    mma_f32(c0[nt], a0, bh[nt][kt][0], bh[nt][kt][1]);
                    mma_f32(c0[nt], a0, bl0, bl1);
                    mma_f32(c1[nt], a1, bh[nt][kt][0], bh[nt][kt][1]);
                    mma_f32(c1[nt], a1, bl0, bl1);
                }
                a0off += 512u; a1off += 512u;
            }
            {
                float* rp = red + wid * 1024 + lane * 4;
#pragma unroll
                for (int nt = 0; nt < 4; nt++) {
                    *(float4*)(rp + nt * 128)       = make_float4(c0[nt][0], c0[nt][1], c0[nt][2], c0[nt][3]);
                    *(float4*)(rp + 512 + nt * 128) = make_float4(c1[nt][0], c1[nt][1], c1[nt][2], c1[nt][3]);
                }
            }
            __syncthreads();   // reduce-sync

            float s0 = 0.f, s1 = 0.f, s2 = 0.f, s3 = 0.f;
#pragma unroll
            for (int w = 0; w < 8; w++) {
                s0 += red[w * 1024 + ebase];
                s1 += red[w * 1024 + ebase + 1];
                s2 += red[w * 1024 + 512 + ebase];
                s3 += red[w * 1024 + 512 + ebase + 1];
            }
            float ve0 = s0 + ue.x, ve1 = s1 + ue.y;
            float vo0 = s2 + uo.x, vo1 = s3 + uo.y;

            float* obe = out + ((size_t)en0 * TB + te) * HB + ejg;
            float* obo = out + ((size_t)en0 * TB + to) * HB + ejg;
            *(float2*)obe = make_float2(ve0, ve1);
            *(float2*)obo = make_float2(vo0, vo1);
            if (two) {
                *(float2*)(obe + NTH) = make_float2(ve0, ve1);
                *(float2*)(obo + NTH) = make_float2(vo0, vo1);
            }

            *(uint32_t*)(&g_ha[s & 1][0][q][ioff]) = packh(ve0, ve1);
            *(uint32_t*)(&g_ha[s & 1][1][q][ioff]) = packh(vo0, vo1);
            asm volatile("fence.proxy.async;" ::: "memory");
            __syncthreads();   // end-sync
        }
    }
}

// ---- launch ----
extern "C" void kernel_launch(void* const* d_in, const int* in_sizes, int n_in,
                              void* d_out, int out_size) {
    const float *x = nullptr, *initial = nullptr, *W_ih = nullptr, *b_ih = nullptr, *W_hh = nullptr;
    for (int i = 0; i < n_in; i++) {
        switch (in_sizes[i]) {
            case 5767168: x = (const float*)d_in[i]; break;
            case 65536:   initial = (const float*)d_in[i]; break;
            case 90112:   W_ih = (const float*)d_in[i]; break;
            case 1024:    b_ih = (const float*)d_in[i]; break;
            case 1048576: W_hh = (const float*)d_in[i]; break;
            default: break;
        }
    }
    float* out = (float*)d_out;
    const long long NTH = (long long)NB * TB * HB;
    int two = ((long long)out_size >= 2 * NTH) ? 1 : 0;

    const int IH_SMEM = (IB * 64 + IB * 128) * 4;
    cudaFuncSetAttribute(ih_kernel, cudaFuncAttributeMaxDynamicSharedMemorySize, IH_SMEM);
    cudaFuncSetAttribute(rnn2_kernel, cudaFuncAttributeMaxDynamicSharedMemorySize, SM_TOT);

    dim3 g1(HB / 128, (NB * TB) / 64);
    ih_kernel<<<g1, 256, IH_SMEM>>>(x, W_ih, b_ih);       // + barrier reset
    w2_kernel<<<dim3(8, 16), 256>>>(W_hh);                 // W^2 fp32
    wprep_kernel<<<1024, 1024>>>(W_hh);                    // W fp16 limb frags
    z_kernel<<<dim3(8, 513), 256>>>(initial);              // z + h1
    rnn2_kernel<<<NCTA, RT2, SM_TOT>>>(initial, out, two);
}